// round 5
// baseline (speedup 1.0000x reference)
#include <cuda_runtime.h>

#define NQ1 10001
#define NC1 301
#define ND1 200
#define NA1 20002

// ---- device scratch (static globals: no runtime allocation) ----
__device__ float g_C23 [128*256];   // [W2|W3]
__device__ float g_W45a[128*256];   // [W4[128:],W5[128:]]
__device__ float g_b45 [256];
__device__ float g_cst23[256];      // b1@C23 + [b2|b3]
__device__ float g_G   [512*256];   // W1 @ C23
__device__ float g_TQ  [NQ1*256];
__device__ float g_TC  [NC1*256];
__device__ float g_TS1 [ND1*256];
__device__ float g_TD1 [ND1*256];
__device__ float g_TA45[NA1*256];
__device__ float g_TA6 [NA1*128];
__device__ float g_TS6 [ND1*128];
__device__ float g_TD6 [ND1*128];

__device__ __forceinline__ float sigm(float x) { return 1.f / (1.f + __expf(-x)); }

// ---------------------------------------------------------------------------
__global__ void prep_concat(const float* __restrict__ W2, const float* __restrict__ W3,
                            const float* __restrict__ W4, const float* __restrict__ W5,
                            const float* __restrict__ b4, const float* __restrict__ b5)
{
    int e = blockIdx.x * 256 + threadIdx.x;
    if (e < 128*256) {
        int i = e >> 8, j = e & 255;
        g_C23 [e] = (j < 128) ? W2[i*128 + j]       : W3[i*128 + (j-128)];
        g_W45a[e] = (j < 128) ? W4[(128+i)*128 + j] : W5[(128+i)*128 + (j-128)];
    }
    if (e < 256) g_b45[e] = (e < 128) ? b4[e] : b5[e-128];
}

__global__ void cst23_kernel(const float* __restrict__ b1, const float* __restrict__ b2,
                             const float* __restrict__ b3)
{
    int j = threadIdx.x;
    float s = (j < 128) ? b2[j] : b3[j-128];
    #pragma unroll 8
    for (int i = 0; i < 128; i++) s += b1[i] * g_C23[i*256 + j];
    g_cst23[j] = s;
}

// C[M,N] = A[M,128] @ B[128,N] (+bias). 256 thr, 32 rows/block, 4 rows/warp.
__global__ void gemm_tab(const float* __restrict__ A, const float* __restrict__ B,
                         const float* __restrict__ bias, float* __restrict__ C,
                         int M, int N)
{
    __shared__ float As[32*128];
    const int tid = threadIdx.x, w = tid >> 5, lane = tid & 31;
    const int row0 = blockIdx.x * 32;
    for (int e = tid; e < 4096; e += 256) {
        int rr = e >> 7, ii = e & 127, gr = row0 + rr;
        As[e] = (gr < M) ? A[gr*128 + ii] : 0.f;
    }
    __syncthreads();
    const int r0 = w * 4;
    for (int jo = 0; jo < N; jo += 128) {
        const int j = jo + lane * 4;
        float acc[4][4] = {};
        const float* Bp = B + j;
        #pragma unroll 4
        for (int i = 0; i < 128; i++) {
            float4 bb = *reinterpret_cast<const float4*>(Bp + i*N);
            #pragma unroll
            for (int rr = 0; rr < 4; rr++) {
                float av = As[(r0 + rr)*128 + i];
                acc[rr][0] += av*bb.x; acc[rr][1] += av*bb.y;
                acc[rr][2] += av*bb.z; acc[rr][3] += av*bb.w;
            }
        }
        float4 bv = bias ? *reinterpret_cast<const float4*>(bias + j)
                         : make_float4(0.f, 0.f, 0.f, 0.f);
        #pragma unroll
        for (int rr = 0; rr < 4; rr++) {
            int row = row0 + r0 + rr;
            if (row < M) {
                float4 o;
                o.x = acc[rr][0]+bv.x; o.y = acc[rr][1]+bv.y;
                o.z = acc[rr][2]+bv.z; o.w = acc[rr][3]+bv.w;
                *reinterpret_cast<float4*>(C + row*N + j) = o;
            }
        }
    }
}

// ---------------------------------------------------------------------------
// scan: one CTA per batch row (128 CTAs, 256 threads).
// Registers: w45 col (128) + W6k half-col (64). SMEM: C23 only (weights).
// ---------------------------------------------------------------------------
#define SCAN_SMEM_FLOATS (32768 + 1280 + 128 + 128 + 256 + 256 + 256)
#define SCAN_SMEM_BYTES  ((SCAN_SMEM_FLOATS + 5*512) * 4)

__global__ void __launch_bounds__(256, 1)
scan_kernel(const int* __restrict__ qi_, const int* __restrict__ ci_,
            const int* __restrict__ si_, const int* __restrict__ di_,
            const int* __restrict__ ai_,
            const float* __restrict__ knowledge,
            const float* __restrict__ W2, const float* __restrict__ W3,
            const float* __restrict__ W4, const float* __restrict__ W5,
            const float* __restrict__ W6,
            const float* __restrict__ Wf, const float* __restrict__ bf,
            float* __restrict__ out)
{
    extern __shared__ float sm[];
    float* C23  = sm;            // 128x256, [i][t] at i*256+t
    float* Wfs  = C23 + 32768;   // 128x10  ([i][o] layout)
    float* kvec = Wfs + 1280;    // 128
    float* sdf  = kvec + 128;    // 128
    float* zb   = sdf + 128;     // 256
    float* g6   = zb + 256;      // 256
    float* pb   = g6 + 256;      // 256
    int*   idxs = (int*)(pb + 256); // 5*512

    const int b = blockIdx.x, t = threadIdx.x;

    for (int e = t; e < 32768; e += 256) {
        int i = e >> 8, j = e & 255;
        C23[e] = (j < 128) ? W2[i*128 + j] : W3[i*128 + (j-128)];
    }
    for (int e = t; e < 1280; e += 256) Wfs[e] = Wf[e];  // [i][o] native layout
    if (t < 128) kvec[t] = knowledge[t];
    for (int e = t; e < 512; e += 256) {
        int g = b*512 + e;
        idxs[e]        = qi_[g];
        idxs[512 + e]  = ci_[g];
        idxs[1024 + e] = si_[g];
        idxs[1536 + e] = di_[g];
        idxs[2048 + e] = ai_[g];
    }

    // register-resident [W4s|W5s] column t (128 regs)
    float w45[128];
    {
        const float* Ws = (t < 128) ? W4 : W5;
        const int col = t & 127;
        #pragma unroll 4
        for (int i = 0; i < 128; i++) w45[i] = Ws[i*128 + col];
    }
    // register-resident W6k half-column: rows [half0, half0+64) of col (t&127)
    const bool low = (t < 128);
    const int half0 = low ? 0 : 64;
    float w6r[64];
    {
        const float* W6c = W6 + half0*128 + (t & 127);
        #pragma unroll 4
        for (int j = 0; j < 64; j++) w6r[j] = W6c[j*128];
    }
    const float bfreg = (t >= 128 && t < 138) ? bf[t-128] : 0.f;
    __syncthreads();

    // prefetch step-0 streams
    float xq, xc, xs, xd, a45p, r6a = 0.f, r6s = 0.f, r6d = 0.f;
    {
        int q0 = idxs[0], c0 = idxs[512], s0 = idxs[1024], d0 = idxs[1536], a0 = idxs[2048];
        xq = g_TQ[q0*256 + t];  xc = g_TC[c0*256 + t];
        xs = g_TS1[s0*256 + t]; xd = g_TD1[d0*256 + t];
        a45p = g_TA45[a0*256 + t];
        if (low) { r6a = g_TA6[a0*128 + t]; r6s = g_TS6[s0*128 + t]; r6d = g_TD6[d0*128 + t]; }
    }

    const float* wcol = C23 + t;
    float* outp = out + b * 5120;

    for (int stp = 0; stp < 512; stp++) {
        const float x23c = (xq + xc) + (xs + xd);
        const float a45c = a45p;
        const float r6c  = (r6a + r6s) + r6d;

        if (stp + 1 < 512) {
            int q1 = idxs[stp+1],      c1 = idxs[512+stp+1], s1 = idxs[1024+stp+1],
                d1 = idxs[1536+stp+1], a1 = idxs[2048+stp+1];
            xq = g_TQ[q1*256 + t];  xc = g_TC[c1*256 + t];
            xs = g_TS1[s1*256 + t]; xd = g_TD1[d1*256 + t];
            a45p = g_TA45[a1*256 + t];
            if (low) { r6a = g_TA6[a1*128 + t]; r6s = g_TS6[s1*128 + t]; r6d = g_TD6[d1*128 + t]; }
        }

        // ---- stage 1: z col t = x23 - k@C23[:,t]; g6 partial = k-half@W6k col ----
        float A0=0.f, A1=0.f, A2=0.f, A3=0.f;
        float G0=0.f, G1=0.f, G2=0.f, G3=0.f;
        if (low) {   // warps 0-3: W6k rows 0..63
            #pragma unroll
            for (int i = 0; i < 64; i += 4) {
                float4 k4 = *reinterpret_cast<const float4*>(kvec + i);
                A0 += k4.x * wcol[(i+0)*256];
                A1 += k4.y * wcol[(i+1)*256];
                A2 += k4.z * wcol[(i+2)*256];
                A3 += k4.w * wcol[(i+3)*256];
                G0 += k4.x * w6r[i+0];
                G1 += k4.y * w6r[i+1];
                G2 += k4.z * w6r[i+2];
                G3 += k4.w * w6r[i+3];
            }
            #pragma unroll
            for (int i = 64; i < 128; i += 4) {
                float4 k4 = *reinterpret_cast<const float4*>(kvec + i);
                A0 += k4.x * wcol[(i+0)*256];
                A1 += k4.y * wcol[(i+1)*256];
                A2 += k4.z * wcol[(i+2)*256];
                A3 += k4.w * wcol[(i+3)*256];
            }
        } else {     // warps 4-7: W6k rows 64..127
            #pragma unroll
            for (int i = 0; i < 64; i += 4) {
                float4 k4 = *reinterpret_cast<const float4*>(kvec + i);
                A0 += k4.x * wcol[(i+0)*256];
                A1 += k4.y * wcol[(i+1)*256];
                A2 += k4.z * wcol[(i+2)*256];
                A3 += k4.w * wcol[(i+3)*256];
            }
            #pragma unroll
            for (int i = 64; i < 128; i += 4) {
                float4 k4 = *reinterpret_cast<const float4*>(kvec + i);
                A0 += k4.x * wcol[(i+0)*256];
                A1 += k4.y * wcol[(i+1)*256];
                A2 += k4.z * wcol[(i+2)*256];
                A3 += k4.w * wcol[(i+3)*256];
                G0 += k4.x * w6r[i-64+0];
                G1 += k4.y * w6r[i-64+1];
                G2 += k4.z * w6r[i-64+2];
                G3 += k4.w * w6r[i-64+3];
            }
        }
        zb[t] = x23c - ((A0+A1)+(A2+A3));
        g6[t] = (G0+G1)+(G2+G3);
        __syncthreads();   // B1

        // ---- stage 2 (t<128): SDFt + gate ----
        float greg = 0.f, kold = 0.f;
        if (low) {
            sdf[t] = sigm(zb[t]) * tanhf(zb[128 + t]);
            greg = sigm(g6[t] + g6[128 + t] + r6c);
            kold = kvec[t];
        }
        __syncthreads();   // B2

        // ---- stage 3: P col t = sdf @ w45 + a45 stream ----
        float P0=0.f, P1=0.f, P2=0.f, P3=0.f;
        #pragma unroll
        for (int i = 0; i < 128; i += 4) {
            float4 s4 = *reinterpret_cast<const float4*>(sdf + i);
            P0 += s4.x * w45[i+0];
            P1 += s4.y * w45[i+1];
            P2 += s4.z * w45[i+2];
            P3 += s4.w * w45[i+3];
        }
        pb[t] = ((P0+P1)+(P2+P3)) + a45c;
        __syncthreads();   // B3

        // ---- stage 4 (t<128): PKAt, k update ----
        if (low) {
            float pka = sigm(pb[t]) * tanhf(pb[128 + t]);
            kvec[t] = greg * kold + (1.f - greg) * pka;
        }
        __syncthreads();   // B4

        // ---- logits: warp 4 lanes 0-9 (skew absorbed by next stage-2 idle) ----
        if (t >= 128 && t < 138) {
            const int o = t - 128;
            float acc = bfreg;
            #pragma unroll 8
            for (int i = 0; i < 128; i++) acc += kvec[i] * Wfs[i*10 + o];
            outp[stp*10 + o] = sigm(acc);
        }
    }
}

// ---------------------------------------------------------------------------
extern "C" void kernel_launch(void* const* d_in, const int* in_sizes, int n_in,
                              void* d_out, int out_size)
{
    const int* qi = (const int*)d_in[0];
    const int* ci = (const int*)d_in[1];
    const int* si = (const int*)d_in[2];
    const int* di = (const int*)d_in[3];
    const int* ai = (const int*)d_in[4];
    const float* knowledge = (const float*)d_in[9];
    const float* q_tab  = (const float*)d_in[10];
    const float* c_tab  = (const float*)d_in[11];
    const float* sd_tab = (const float*)d_in[12];
    const float* qd_tab = (const float*)d_in[13];
    const float* a_tab  = (const float*)d_in[14];
    const float* W1 = (const float*)d_in[15]; const float* b1 = (const float*)d_in[16];
    const float* W2 = (const float*)d_in[17]; const float* b2 = (const float*)d_in[18];
    const float* W3 = (const float*)d_in[19]; const float* b3 = (const float*)d_in[20];
    const float* W4 = (const float*)d_in[21]; const float* b4 = (const float*)d_in[22];
    const float* W5 = (const float*)d_in[23]; const float* b5 = (const float*)d_in[24];
    const float* W6 = (const float*)d_in[25]; const float* b6 = (const float*)d_in[26];
    const float* Wf = (const float*)d_in[27]; const float* bf = (const float*)d_in[28];
    float* out = (float*)d_out;

    float *pC23, *pW45a, *pb45, *pcst, *pG, *pTQ, *pTC, *pTS1, *pTD1, *pTA45, *pTA6, *pTS6, *pTD6;
    cudaGetSymbolAddress((void**)&pC23,  g_C23);
    cudaGetSymbolAddress((void**)&pW45a, g_W45a);
    cudaGetSymbolAddress((void**)&pb45,  g_b45);
    cudaGetSymbolAddress((void**)&pcst,  g_cst23);
    cudaGetSymbolAddress((void**)&pG,    g_G);
    cudaGetSymbolAddress((void**)&pTQ,   g_TQ);
    cudaGetSymbolAddress((void**)&pTC,   g_TC);
    cudaGetSymbolAddress((void**)&pTS1,  g_TS1);
    cudaGetSymbolAddress((void**)&pTD1,  g_TD1);
    cudaGetSymbolAddress((void**)&pTA45, g_TA45);
    cudaGetSymbolAddress((void**)&pTA6,  g_TA6);
    cudaGetSymbolAddress((void**)&pTS6,  g_TS6);
    cudaGetSymbolAddress((void**)&pTD6,  g_TD6);

    prep_concat<<<128, 256>>>(W2, W3, W4, W5, b4, b5);
    cst23_kernel<<<1, 256>>>(b1, b2, b3);
    gemm_tab<<<16, 256>>>(W1, pC23, nullptr, pG, 512, 256);
    gemm_tab<<<(NQ1+31)/32, 256>>>(q_tab,  pG,           pcst,    pTQ,   NQ1, 256);
    gemm_tab<<<(NC1+31)/32, 256>>>(c_tab,  pG + 128*256, nullptr, pTC,   NC1, 256);
    gemm_tab<<<(ND1+31)/32, 256>>>(sd_tab, pG + 256*256, nullptr, pTS1,  ND1, 256);
    gemm_tab<<<(ND1+31)/32, 256>>>(qd_tab, pG + 384*256, nullptr, pTD1,  ND1, 256);
    gemm_tab<<<(NA1+31)/32, 256>>>(a_tab,  pW45a,        pb45,    pTA45, NA1, 256);
    gemm_tab<<<(NA1+31)/32, 256>>>(a_tab,  W6 + 128*128, b6,      pTA6,  NA1, 128);
    gemm_tab<<<(ND1+31)/32, 256>>>(sd_tab, W6 + 256*128, nullptr, pTS6,  ND1, 128);
    gemm_tab<<<(ND1+31)/32, 256>>>(qd_tab, W6 + 384*128, nullptr, pTD6,  ND1, 128);

    cudaFuncSetAttribute(scan_kernel, cudaFuncAttributeMaxDynamicSharedMemorySize, SCAN_SMEM_BYTES);
    scan_kernel<<<128, 256, SCAN_SMEM_BYTES>>>(qi, ci, si, di, ai, knowledge,
                                               W2, W3, W4, W5, W6, Wf, bf, out);
}

// round 6
// speedup vs baseline: 1.4324x; 1.4324x over previous
#include <cuda_runtime.h>

#define NQ1 10001
#define NC1 301
#define ND1 200
#define NA1 20002

// ---- device scratch (static globals: no runtime allocation) ----
__device__ float g_C23 [128*256];   // [W2|W3]
__device__ float g_W45a[128*256];   // [W4[128:],W5[128:]]
__device__ float g_b45 [256];
__device__ float g_cst23[256];      // b1@C23 + [b2|b3]
__device__ float g_G   [512*256];   // W1 @ C23
__device__ float g_TQ  [NQ1*256];
__device__ float g_TC  [NC1*256];
__device__ float g_TS1 [ND1*256];
__device__ float g_TD1 [ND1*256];
__device__ float g_TA45[NA1*256];
__device__ float g_TA6 [NA1*128];
__device__ float g_TS6 [ND1*128];
__device__ float g_TD6 [ND1*128];

__device__ __forceinline__ float sigm(float x) { return 1.f / (1.f + __expf(-x)); }

// ---------------------------------------------------------------------------
__global__ void prep_concat(const float* __restrict__ W2, const float* __restrict__ W3,
                            const float* __restrict__ W4, const float* __restrict__ W5,
                            const float* __restrict__ b4, const float* __restrict__ b5)
{
    int e = blockIdx.x * 256 + threadIdx.x;
    if (e < 128*256) {
        int i = e >> 8, j = e & 255;
        g_C23 [e] = (j < 128) ? W2[i*128 + j]       : W3[i*128 + (j-128)];
        g_W45a[e] = (j < 128) ? W4[(128+i)*128 + j] : W5[(128+i)*128 + (j-128)];
    }
    if (e < 256) g_b45[e] = (e < 128) ? b4[e] : b5[e-128];
}

__global__ void cst23_kernel(const float* __restrict__ b1, const float* __restrict__ b2,
                             const float* __restrict__ b3)
{
    int j = threadIdx.x;
    float s = (j < 128) ? b2[j] : b3[j-128];
    #pragma unroll 8
    for (int i = 0; i < 128; i++) s += b1[i] * g_C23[i*256 + j];
    g_cst23[j] = s;
}

// ---------------------------------------------------------------------------
// batched table GEMM: up to 4 independent C[M,N] = A[M,128]@B[128,N] (+bias)
// 256 thr, 32 rows/block, 4 rows/warp. Descriptors passed by value.
// ---------------------------------------------------------------------------
struct GDesc { const float *A, *B, *bias; float *C; int M, N; };
struct GBatch { GDesc g[4]; int start[5]; };   // start[i]: first block of gemm i

__global__ void gemm_batched(GBatch bt)
{
    __shared__ float As[32*128];
    int gi = 0;
    while (gi < 3 && (int)blockIdx.x >= bt.start[gi+1]) gi++;
    const GDesc d = bt.g[gi];
    const int blk = blockIdx.x - bt.start[gi];

    const int tid = threadIdx.x, w = tid >> 5, lane = tid & 31;
    const int row0 = blk * 32;
    for (int e = tid; e < 4096; e += 256) {
        int rr = e >> 7, ii = e & 127, gr = row0 + rr;
        As[e] = (gr < d.M) ? d.A[gr*128 + ii] : 0.f;
    }
    __syncthreads();
    const int r0 = w * 4;
    for (int jo = 0; jo < d.N; jo += 128) {
        const int j = jo + lane * 4;
        float acc[4][4] = {};
        const float* Bp = d.B + j;
        #pragma unroll 4
        for (int i = 0; i < 128; i++) {
            float4 bb = *reinterpret_cast<const float4*>(Bp + i*d.N);
            #pragma unroll
            for (int rr = 0; rr < 4; rr++) {
                float av = As[(r0 + rr)*128 + i];
                acc[rr][0] += av*bb.x; acc[rr][1] += av*bb.y;
                acc[rr][2] += av*bb.z; acc[rr][3] += av*bb.w;
            }
        }
        float4 bv = d.bias ? *reinterpret_cast<const float4*>(d.bias + j)
                           : make_float4(0.f, 0.f, 0.f, 0.f);
        #pragma unroll
        for (int rr = 0; rr < 4; rr++) {
            int row = row0 + r0 + rr;
            if (row < d.M) {
                float4 o;
                o.x = acc[rr][0]+bv.x; o.y = acc[rr][1]+bv.y;
                o.z = acc[rr][2]+bv.z; o.w = acc[rr][3]+bv.w;
                *reinterpret_cast<float4*>(d.C + row*d.N + j) = o;
            }
        }
    }
}

// single (non-batched) GEMM for g_G
__global__ void gemm_tab(const float* __restrict__ A, const float* __restrict__ B,
                         float* __restrict__ C, int M, int N)
{
    __shared__ float As[32*128];
    const int tid = threadIdx.x, w = tid >> 5, lane = tid & 31;
    const int row0 = blockIdx.x * 32;
    for (int e = tid; e < 4096; e += 256) {
        int rr = e >> 7, ii = e & 127, gr = row0 + rr;
        As[e] = (gr < M) ? A[gr*128 + ii] : 0.f;
    }
    __syncthreads();
    const int r0 = w * 4;
    for (int jo = 0; jo < N; jo += 128) {
        const int j = jo + lane * 4;
        float acc[4][4] = {};
        const float* Bp = B + j;
        #pragma unroll 4
        for (int i = 0; i < 128; i++) {
            float4 bb = *reinterpret_cast<const float4*>(Bp + i*N);
            #pragma unroll
            for (int rr = 0; rr < 4; rr++) {
                float av = As[(r0 + rr)*128 + i];
                acc[rr][0] += av*bb.x; acc[rr][1] += av*bb.y;
                acc[rr][2] += av*bb.z; acc[rr][3] += av*bb.w;
            }
        }
        #pragma unroll
        for (int rr = 0; rr < 4; rr++) {
            int row = row0 + r0 + rr;
            if (row < M) {
                float4 o = { acc[rr][0], acc[rr][1], acc[rr][2], acc[rr][3] };
                *reinterpret_cast<float4*>(C + row*N + j) = o;
            }
        }
    }
}

// ---------------------------------------------------------------------------
// scan: one CTA per batch row (128 CTAs, 256 threads).
// w45 column truly register-resident (all indices static). W6k in SMEM.
// ---------------------------------------------------------------------------
#define SCAN_SMEM_BYTES ((32768 + 16384 + 1280 + 128 + 128 + 256 + 256 + 256 + 80 + 2560) * 4)

__global__ void __launch_bounds__(256, 1)
scan_kernel(const int* __restrict__ qi_, const int* __restrict__ ci_,
            const int* __restrict__ si_, const int* __restrict__ di_,
            const int* __restrict__ ai_,
            const float* __restrict__ knowledge,
            const float* __restrict__ W2, const float* __restrict__ W3,
            const float* __restrict__ W4, const float* __restrict__ W5,
            const float* __restrict__ W6,
            const float* __restrict__ Wf, const float* __restrict__ bf,
            float* __restrict__ out)
{
    extern __shared__ float sm[];
    float* C23  = sm;            // 128x256, [i][t] at i*256+t
    float* W6k  = C23 + 32768;   // 128x128
    float* Wfs  = W6k + 16384;   // 10x128 (transposed Wf)
    float* kvec = Wfs + 1280;    // 128
    float* sdf  = kvec + 128;    // 128
    float* zb   = sdf + 128;     // 256
    float* g6   = zb + 256;      // 256
    float* pb   = g6 + 256;      // 256
    float* lp   = pb + 256;      // 80
    int*   idxs = (int*)(lp + 80); // 5*512

    const int b = blockIdx.x, t = threadIdx.x;

    for (int e = t; e < 32768; e += 256) {
        int i = e >> 8, j = e & 255;
        C23[e] = (j < 128) ? W2[i*128 + j] : W3[i*128 + (j-128)];
    }
    for (int e = t; e < 16384; e += 256) W6k[e] = W6[e];
    for (int e = t; e < 1280; e += 256) { int o = e >> 7, i = e & 127; Wfs[e] = Wf[i*10 + o]; }
    if (t < 128) kvec[t] = knowledge[t];
    for (int e = t; e < 512; e += 256) {
        int g = b*512 + e;
        idxs[e]        = qi_[g];
        idxs[512 + e]  = ci_[g];
        idxs[1024 + e] = si_[g];
        idxs[1536 + e] = di_[g];
        idxs[2048 + e] = ai_[g];
    }
    // register-resident [W4s|W5s] column t — FULLY unrolled init (static idx)
    float w45[128];
    {
        const float* Ws = (t < 128) ? W4 : W5;
        const int col = t & 127;
        #pragma unroll
        for (int i = 0; i < 128; i++) w45[i] = Ws[i*128 + col];
    }
    const float bfreg = (t < 10) ? bf[t] : 0.f;
    __syncthreads();

    const bool low = (t < 128);

    // prefetch step-0 streams
    float xq, xc, xs, xd, a45p, r6a = 0.f, r6s = 0.f, r6d = 0.f;
    {
        int q0 = idxs[0], c0 = idxs[512], s0 = idxs[1024], d0 = idxs[1536], a0 = idxs[2048];
        xq = g_TQ[q0*256 + t];  xc = g_TC[c0*256 + t];
        xs = g_TS1[s0*256 + t]; xd = g_TD1[d0*256 + t];
        a45p = g_TA45[a0*256 + t];
        if (low) { r6a = g_TA6[a0*128 + t]; r6s = g_TS6[s0*128 + t]; r6d = g_TD6[d0*128 + t]; }
    }

    const float* wcol = C23 + t;
    const float* w6c  = W6k + (t & 127);
    const int half0   = (t >> 7) * 64;
    float* outp = out + b * 5120;

    for (int stp = 0; stp < 512; stp++) {
        const float x23c = (xq + xc) + (xs + xd);
        const float a45c = a45p;
        const float r6c  = (r6a + r6s) + r6d;

        if (stp + 1 < 512) {
            int q1 = idxs[stp+1],      c1 = idxs[512+stp+1], s1 = idxs[1024+stp+1],
                d1 = idxs[1536+stp+1], a1 = idxs[2048+stp+1];
            xq = g_TQ[q1*256 + t];  xc = g_TC[c1*256 + t];
            xs = g_TS1[s1*256 + t]; xd = g_TD1[d1*256 + t];
            a45p = g_TA45[a1*256 + t];
            if (low) { r6a = g_TA6[a1*128 + t]; r6s = g_TS6[s1*128 + t]; r6d = g_TD6[d1*128 + t]; }
        }

        // stage 1: z col t = x23 - k@C23[:,t]; g6 partial = k-half@W6k col
        float A0=0.f,A1=0.f,A2=0.f,A3=0.f;
        #pragma unroll
        for (int i = 0; i < 128; i += 4) {
            float4 k4 = *reinterpret_cast<const float4*>(kvec + i);
            A0 += k4.x * wcol[(i+0)*256];
            A1 += k4.y * wcol[(i+1)*256];
            A2 += k4.z * wcol[(i+2)*256];
            A3 += k4.w * wcol[(i+3)*256];
        }
        float G0=0.f,G1=0.f,G2=0.f,G3=0.f;
        #pragma unroll
        for (int i = 0; i < 64; i += 4) {
            int ii = half0 + i;
            float4 k4 = *reinterpret_cast<const float4*>(kvec + ii);
            G0 += k4.x * w6c[(ii+0)*128];
            G1 += k4.y * w6c[(ii+1)*128];
            G2 += k4.z * w6c[(ii+2)*128];
            G3 += k4.w * w6c[(ii+3)*128];
        }
        zb[t] = x23c - ((A0+A1)+(A2+A3));
        g6[t] = (G0+G1)+(G2+G3);
        __syncthreads();

        // stage 2 (t<128): SDFt + gate
        float greg = 0.f, kold = 0.f;
        if (low) {
            sdf[t] = sigm(zb[t]) * tanhf(zb[128 + t]);
            greg = sigm(g6[t] + g6[128 + t] + r6c);
            kold = kvec[t];
        }
        __syncthreads();

        // stage 3: P col t = sdf @ w45 + a45 stream (w45 in registers)
        float P0=0.f,P1=0.f,P2=0.f,P3=0.f;
        #pragma unroll
        for (int i = 0; i < 128; i += 4) {
            float4 s4 = *reinterpret_cast<const float4*>(sdf + i);
            P0 += s4.x * w45[i+0];
            P1 += s4.y * w45[i+1];
            P2 += s4.z * w45[i+2];
            P3 += s4.w * w45[i+3];
        }
        pb[t] = ((P0+P1)+(P2+P3)) + a45c;
        __syncthreads();

        // stage 4 (t<128): PKAt, k update
        if (low) {
            float pka = sigm(pb[t]) * tanhf(pb[128 + t]);
            kvec[t] = greg * kold + (1.f - greg) * pka;
        }
        __syncthreads();

        // stage 5: logits partials (t<80): out o = t>>3, seg = (t&7)*16
        if (t < 80) {
            int o = t >> 3, s0i = (t & 7) * 16;
            const float* wf = Wfs + o*128 + s0i;
            const float* kk = kvec + s0i;
            float acc = 0.f;
            #pragma unroll
            for (int i = 0; i < 16; i += 4) {
                float4 k4 = *reinterpret_cast<const float4*>(kk + i);
                acc += k4.x*wf[i] + k4.y*wf[i+1] + k4.z*wf[i+2] + k4.w*wf[i+3];
            }
            lp[t] = acc;
        }
        __syncthreads();

        if (t < 10) {
            float acc = bfreg;
            #pragma unroll
            for (int u = 0; u < 8; u++) acc += lp[t*8 + u];
            outp[stp*10 + t] = sigm(acc);
        }
        __syncthreads();
    }
}

// ---------------------------------------------------------------------------
extern "C" void kernel_launch(void* const* d_in, const int* in_sizes, int n_in,
                              void* d_out, int out_size)
{
    const int* qi = (const int*)d_in[0];
    const int* ci = (const int*)d_in[1];
    const int* si = (const int*)d_in[2];
    const int* di = (const int*)d_in[3];
    const int* ai = (const int*)d_in[4];
    const float* knowledge = (const float*)d_in[9];
    const float* q_tab  = (const float*)d_in[10];
    const float* c_tab  = (const float*)d_in[11];
    const float* sd_tab = (const float*)d_in[12];
    const float* qd_tab = (const float*)d_in[13];
    const float* a_tab  = (const float*)d_in[14];
    const float* W1 = (const float*)d_in[15]; const float* b1 = (const float*)d_in[16];
    const float* W2 = (const float*)d_in[17]; const float* b2 = (const float*)d_in[18];
    const float* W3 = (const float*)d_in[19]; const float* b3 = (const float*)d_in[20];
    const float* W4 = (const float*)d_in[21]; const float* b4 = (const float*)d_in[22];
    const float* W5 = (const float*)d_in[23]; const float* b5 = (const float*)d_in[24];
    const float* W6 = (const float*)d_in[25]; const float* b6 = (const float*)d_in[26];
    const float* Wf = (const float*)d_in[27]; const float* bf = (const float*)d_in[28];
    float* out = (float*)d_out;

    float *pC23, *pW45a, *pb45, *pcst, *pG, *pTQ, *pTC, *pTS1, *pTD1, *pTA45, *pTA6, *pTS6, *pTD6;
    cudaGetSymbolAddress((void**)&pC23,  g_C23);
    cudaGetSymbolAddress((void**)&pW45a, g_W45a);
    cudaGetSymbolAddress((void**)&pb45,  g_b45);
    cudaGetSymbolAddress((void**)&pcst,  g_cst23);
    cudaGetSymbolAddress((void**)&pG,    g_G);
    cudaGetSymbolAddress((void**)&pTQ,   g_TQ);
    cudaGetSymbolAddress((void**)&pTC,   g_TC);
    cudaGetSymbolAddress((void**)&pTS1,  g_TS1);
    cudaGetSymbolAddress((void**)&pTD1,  g_TD1);
    cudaGetSymbolAddress((void**)&pTA45, g_TA45);
    cudaGetSymbolAddress((void**)&pTA6,  g_TA6);
    cudaGetSymbolAddress((void**)&pTS6,  g_TS6);
    cudaGetSymbolAddress((void**)&pTD6,  g_TD6);

    // launch 0,1: prep
    prep_concat<<<128, 256>>>(W2, W3, W4, W5, b4, b5);
    cst23_kernel<<<1, 256>>>(b1, b2, b3);
    // launch 2: g_G = W1 @ C23
    gemm_tab<<<16, 256>>>(W1, pC23, pG, 512, 256);

    // launch 3: batch A (independent of g_G): TA45, TA6, TS6, TD6
    {
        GBatch bt;
        bt.g[0] = { a_tab,  pW45a,        pb45,    pTA45, NA1, 256 };
        bt.g[1] = { a_tab,  W6 + 128*128, b6,      pTA6,  NA1, 128 };
        bt.g[2] = { sd_tab, W6 + 256*128, nullptr, pTS6,  ND1, 128 };
        bt.g[3] = { qd_tab, W6 + 384*128, nullptr, pTD6,  ND1, 128 };
        int s = 0; bt.start[0] = 0;
        for (int i = 0; i < 4; i++) { s += (bt.g[i].M + 31) / 32; bt.start[i+1] = s; }
        gemm_batched<<<s, 256>>>(bt);
    }
    // launch 4: batch B (needs g_G): TQ, TC, TS1, TD1
    {
        GBatch bt;
        bt.g[0] = { q_tab,  pG,           pcst,    pTQ,  NQ1, 256 };
        bt.g[1] = { c_tab,  pG + 128*256, nullptr, pTC,  NC1, 256 };
        bt.g[2] = { sd_tab, pG + 256*256, nullptr, pTS1, ND1, 256 };
        bt.g[3] = { qd_tab, pG + 384*256, nullptr, pTD1, ND1, 256 };
        int s = 0; bt.start[0] = 0;
        for (int i = 0; i < 4; i++) { s += (bt.g[i].M + 31) / 32; bt.start[i+1] = s; }
        gemm_batched<<<s, 256>>>(bt);
    }

    // launch 5: scan (profiled by ncu -s 5 -c 1)
    cudaFuncSetAttribute(scan_kernel, cudaFuncAttributeMaxDynamicSharedMemorySize, SCAN_SMEM_BYTES);
    scan_kernel<<<128, 256, SCAN_SMEM_BYTES>>>(qi, ci, si, di, ai, knowledge,
                                               W2, W3, W4, W5, W6, Wf, bf, out);
}

// round 7
// speedup vs baseline: 1.5849x; 1.1065x over previous
#include <cuda_runtime.h>

#define NQ1 10001
#define NC1 301
#define ND1 200
#define NA1 20002

// ---- device scratch (static globals: no runtime allocation) ----
__device__ float g_C23 [128*256];   // [W2|W3] row-major (GEMM B operand)
__device__ float g_W45a[128*256];   // [W4[128:],W5[128:]]
__device__ float g_b45 [256];
__device__ float g_b23 [256];       // [b2|b3]
__device__ float g_cst23[256];      // b1@C23 + [b2|b3]
__device__ float g_G   [512*256];   // W1 @ C23
__device__ float g_TQ  [NQ1*256];
__device__ float g_TC  [NC1*256];
__device__ float g_TS1 [ND1*256];
__device__ float g_TD1 [ND1*256];
__device__ float g_TA45[NA1*256];
__device__ float g_TA6 [NA1*128];
__device__ float g_TS6 [ND1*128];
__device__ float g_TD6 [ND1*128];

__device__ __forceinline__ float sigm(float x) { return 1.f / (1.f + __expf(-x)); }
__device__ __forceinline__ float tanh_fast(float x) {
    float y; asm("tanh.approx.f32 %0, %1;" : "=f"(y) : "f"(x)); return y;
}

// ---------------------------------------------------------------------------
__global__ void prep_concat(const float* __restrict__ W2, const float* __restrict__ W3,
                            const float* __restrict__ W4, const float* __restrict__ W5,
                            const float* __restrict__ b2, const float* __restrict__ b3,
                            const float* __restrict__ b4, const float* __restrict__ b5)
{
    int e = blockIdx.x * 256 + threadIdx.x;
    if (e < 128*256) {
        int i = e >> 8, j = e & 255;
        g_C23 [e] = (j < 128) ? W2[i*128 + j]       : W3[i*128 + (j-128)];
        g_W45a[e] = (j < 128) ? W4[(128+i)*128 + j] : W5[(128+i)*128 + (j-128)];
    }
    if (e < 256) {
        g_b45[e] = (e < 128) ? b4[e] : b5[e-128];
        g_b23[e] = (e < 128) ? b2[e] : b3[e-128];
    }
}

// ---------------------------------------------------------------------------
// batched table GEMM: up to 6 independent C[M,N] = A[M,128]@B[128,N] (+bias)
// 256 thr, 32 rows/block, 4 rows/warp.
// ---------------------------------------------------------------------------
struct GDesc { const float *A, *B, *bias; float *C; int M, N; };
struct GBatch { GDesc g[6]; int start[7]; int n; };

__global__ void gemm_batched(GBatch bt)
{
    __shared__ float As[32*128];
    int gi = 0;
    while (gi < bt.n - 1 && (int)blockIdx.x >= bt.start[gi+1]) gi++;
    const GDesc d = bt.g[gi];
    const int blk = blockIdx.x - bt.start[gi];

    const int tid = threadIdx.x, w = tid >> 5, lane = tid & 31;
    const int row0 = blk * 32;
    for (int e = tid; e < 4096; e += 256) {
        int rr = e >> 7, ii = e & 127, gr = row0 + rr;
        As[e] = (gr < d.M) ? d.A[gr*128 + ii] : 0.f;
    }
    __syncthreads();
    const int r0 = w * 4;
    for (int jo = 0; jo < d.N; jo += 128) {
        const int j = jo + lane * 4;
        float acc[4][4] = {};
        const float* Bp = d.B + j;
        #pragma unroll 4
        for (int i = 0; i < 128; i++) {
            float4 bb = *reinterpret_cast<const float4*>(Bp + i*d.N);
            #pragma unroll
            for (int rr = 0; rr < 4; rr++) {
                float av = As[(r0 + rr)*128 + i];
                acc[rr][0] += av*bb.x; acc[rr][1] += av*bb.y;
                acc[rr][2] += av*bb.z; acc[rr][3] += av*bb.w;
            }
        }
        float4 bv = d.bias ? *reinterpret_cast<const float4*>(d.bias + j)
                           : make_float4(0.f, 0.f, 0.f, 0.f);
        #pragma unroll
        for (int rr = 0; rr < 4; rr++) {
            int row = row0 + r0 + rr;
            if (row < d.M) {
                float4 o;
                o.x = acc[rr][0]+bv.x; o.y = acc[rr][1]+bv.y;
                o.z = acc[rr][2]+bv.z; o.w = acc[rr][3]+bv.w;
                *reinterpret_cast<float4*>(d.C + row*d.N + j) = o;
            }
        }
    }
}

// ---------------------------------------------------------------------------
// scan: one CTA per batch row (128 CTAs, 256 threads).
// C23 / W6k stored TRANSPOSED + padded (stride 132) in SMEM -> LDS.128 reads.
// w45 column register-resident. tanh via MUFU.
// ---------------------------------------------------------------------------
#define C23T_STRIDE 132
#define SCAN_SMEM_FLOATS (256*132 + 128*132 + 1280 + 128 + 128 + 256 + 256 + 256 + 80)
#define SCAN_SMEM_BYTES  ((SCAN_SMEM_FLOATS + 5*512) * 4)

__global__ void __launch_bounds__(256, 1)
scan_kernel(const int* __restrict__ qi_, const int* __restrict__ ci_,
            const int* __restrict__ si_, const int* __restrict__ di_,
            const int* __restrict__ ai_,
            const float* __restrict__ knowledge,
            const float* __restrict__ W2, const float* __restrict__ W3,
            const float* __restrict__ W4, const float* __restrict__ W5,
            const float* __restrict__ W6,
            const float* __restrict__ Wf, const float* __restrict__ bf,
            float* __restrict__ out)
{
    extern __shared__ float sm[];
    float* C23t = sm;                    // [col][i], stride 132, col<256
    float* W6t  = C23t + 256*132;        // [col][i], stride 132, col<128
    float* Wfs  = W6t + 128*132;         // 10x128 ([o][i])
    float* kvec = Wfs + 1280;            // 128
    float* sdf  = kvec + 128;            // 128
    float* zb   = sdf + 128;             // 256
    float* g6   = zb + 256;              // 256
    float* pb   = g6 + 256;              // 256
    float* lp   = pb + 256;              // 80
    int*   idxs = (int*)(lp + 80);       // 5*512

    const int b = blockIdx.x, t = threadIdx.x;

    // transposed fills (coalesced global reads)
    for (int e = t; e < 128*256; e += 256) {
        int i = e >> 8, j = e & 255;
        float v = (j < 128) ? W2[i*128 + j] : W3[i*128 + (j-128)];
        C23t[j*C23T_STRIDE + i] = v;
    }
    for (int e = t; e < 128*128; e += 256) {
        int i = e >> 7, c = e & 127;
        W6t[c*C23T_STRIDE + i] = W6[i*128 + c];
    }
    for (int e = t; e < 1280; e += 256) { int o = e >> 7, i = e & 127; Wfs[e] = Wf[i*10 + o]; }
    if (t < 128) kvec[t] = knowledge[t];
    for (int e = t; e < 512; e += 256) {
        int g = b*512 + e;
        idxs[e]        = qi_[g];
        idxs[512 + e]  = ci_[g];
        idxs[1024 + e] = si_[g];
        idxs[1536 + e] = di_[g];
        idxs[2048 + e] = ai_[g];
    }
    // register-resident [W4s|W5s] column t (fully unrolled -> true registers)
    float w45[128];
    {
        const float* Ws = (t < 128) ? W4 : W5;
        const int col = t & 127;
        #pragma unroll
        for (int i = 0; i < 128; i++) w45[i] = Ws[i*128 + col];
    }
    const float bfreg = (t < 10) ? bf[t] : 0.f;
    __syncthreads();

    const bool low = (t < 128);
    const int half0 = (t >> 7) * 64;

    // prefetch step-0 streams
    float xq, xc, xs, xd, a45p, r6a = 0.f, r6s = 0.f, r6d = 0.f;
    {
        int q0 = idxs[0], c0 = idxs[512], s0 = idxs[1024], d0 = idxs[1536], a0 = idxs[2048];
        xq = g_TQ[q0*256 + t];  xc = g_TC[c0*256 + t];
        xs = g_TS1[s0*256 + t]; xd = g_TD1[d0*256 + t];
        a45p = g_TA45[a0*256 + t];
        if (low) { r6a = g_TA6[a0*128 + t]; r6s = g_TS6[s0*128 + t]; r6d = g_TD6[d0*128 + t]; }
    }

    const float* wc = C23t + t*C23T_STRIDE;
    const float* w6 = W6t + (t & 127)*C23T_STRIDE + half0;
    float* outp = out + b * 5120;

    for (int stp = 0; stp < 512; stp++) {
        const float x23c = (xq + xc) + (xs + xd);
        const float a45c = a45p;
        const float r6c  = (r6a + r6s) + r6d;

        if (stp + 1 < 512) {
            int q1 = idxs[stp+1],      c1 = idxs[512+stp+1], s1 = idxs[1024+stp+1],
                d1 = idxs[1536+stp+1], a1 = idxs[2048+stp+1];
            xq = g_TQ[q1*256 + t];  xc = g_TC[c1*256 + t];
            xs = g_TS1[s1*256 + t]; xd = g_TD1[d1*256 + t];
            a45p = g_TA45[a1*256 + t];
            if (low) { r6a = g_TA6[a1*128 + t]; r6s = g_TS6[s1*128 + t]; r6d = g_TD6[d1*128 + t]; }
        }

        // ---- stage 1: z col t = x23 - k@C23[:,t] ; g6 partial via W6t ----
        float A0=0.f,A1=0.f,A2=0.f,A3=0.f;
        #pragma unroll
        for (int i = 0; i < 128; i += 4) {
            float4 k4 = *reinterpret_cast<const float4*>(kvec + i);
            float4 w4 = *reinterpret_cast<const float4*>(wc + i);
            A0 += k4.x * w4.x;
            A1 += k4.y * w4.y;
            A2 += k4.z * w4.z;
            A3 += k4.w * w4.w;
        }
        float G0=0.f,G1=0.f,G2=0.f,G3=0.f;
        #pragma unroll
        for (int i = 0; i < 64; i += 4) {
            float4 k4 = *reinterpret_cast<const float4*>(kvec + half0 + i);
            float4 w4 = *reinterpret_cast<const float4*>(w6 + i);
            G0 += k4.x * w4.x;
            G1 += k4.y * w4.y;
            G2 += k4.z * w4.z;
            G3 += k4.w * w4.w;
        }
        zb[t] = x23c - ((A0+A1)+(A2+A3));
        g6[t] = (G0+G1)+(G2+G3);
        __syncthreads();

        // ---- stage 2 (t<128): SDFt + gate ----
        float greg = 0.f, kold = 0.f;
        if (low) {
            sdf[t] = sigm(zb[t]) * tanh_fast(zb[128 + t]);
            greg = sigm(g6[t] + g6[128 + t] + r6c);
            kold = kvec[t];
        }
        __syncthreads();

        // ---- stage 3: P col t = sdf @ w45 + a45 stream (w45 in registers) ----
        float P0=0.f,P1=0.f,P2=0.f,P3=0.f;
        #pragma unroll
        for (int i = 0; i < 128; i += 4) {
            float4 s4 = *reinterpret_cast<const float4*>(sdf + i);
            P0 += s4.x * w45[i+0];
            P1 += s4.y * w45[i+1];
            P2 += s4.z * w45[i+2];
            P3 += s4.w * w45[i+3];
        }
        pb[t] = ((P0+P1)+(P2+P3)) + a45c;
        __syncthreads();

        // ---- stage 4 (t<128): PKAt, k update ----
        if (low) {
            float pka = sigm(pb[t]) * tanh_fast(pb[128 + t]);
            kvec[t] = greg * kold + (1.f - greg) * pka;
        }
        __syncthreads();

        // ---- stage 5: logits partials (t<80) ----
        if (t < 80) {
            int o = t >> 3, s0i = (t & 7) * 16;
            const float* wf = Wfs + o*128 + s0i;
            const float* kk = kvec + s0i;
            float acc = 0.f;
            #pragma unroll
            for (int i = 0; i < 16; i += 4) {
                float4 k4 = *reinterpret_cast<const float4*>(kk + i);
                acc += k4.x*wf[i] + k4.y*wf[i+1] + k4.z*wf[i+2] + k4.w*wf[i+3];
            }
            lp[t] = acc;
        }
        __syncthreads();

        if (t < 10) {
            float acc = bfreg;
            #pragma unroll
            for (int u = 0; u < 8; u++) acc += lp[t*8 + u];
            outp[stp*10 + t] = sigm(acc);
        }
        __syncthreads();
    }
}

// ---------------------------------------------------------------------------
extern "C" void kernel_launch(void* const* d_in, const int* in_sizes, int n_in,
                              void* d_out, int out_size)
{
    const int* qi = (const int*)d_in[0];
    const int* ci = (const int*)d_in[1];
    const int* si = (const int*)d_in[2];
    const int* di = (const int*)d_in[3];
    const int* ai = (const int*)d_in[4];
    const float* knowledge = (const float*)d_in[9];
    const float* q_tab  = (const float*)d_in[10];
    const float* c_tab  = (const float*)d_in[11];
    const float* sd_tab = (const float*)d_in[12];
    const float* qd_tab = (const float*)d_in[13];
    const float* a_tab  = (const float*)d_in[14];
    const float* W1 = (const float*)d_in[15]; const float* b1 = (const float*)d_in[16];
    const float* W2 = (const float*)d_in[17]; const float* b2 = (const float*)d_in[18];
    const float* W3 = (const float*)d_in[19]; const float* b3 = (const float*)d_in[20];
    const float* W4 = (const float*)d_in[21]; const float* b4 = (const float*)d_in[22];
    const float* W5 = (const float*)d_in[23]; const float* b5 = (const float*)d_in[24];
    const float* W6 = (const float*)d_in[25]; const float* b6 = (const float*)d_in[26];
    const float* Wf = (const float*)d_in[27]; const float* bf = (const float*)d_in[28];
    float* out = (float*)d_out;

    float *pC23, *pW45a, *pb45, *pb23, *pcst, *pG, *pTQ, *pTC, *pTS1, *pTD1, *pTA45, *pTA6, *pTS6, *pTD6;
    cudaGetSymbolAddress((void**)&pC23,  g_C23);
    cudaGetSymbolAddress((void**)&pW45a, g_W45a);
    cudaGetSymbolAddress((void**)&pb45,  g_b45);
    cudaGetSymbolAddress((void**)&pb23,  g_b23);
    cudaGetSymbolAddress((void**)&pcst,  g_cst23);
    cudaGetSymbolAddress((void**)&pG,    g_G);
    cudaGetSymbolAddress((void**)&pTQ,   g_TQ);
    cudaGetSymbolAddress((void**)&pTC,   g_TC);
    cudaGetSymbolAddress((void**)&pTS1,  g_TS1);
    cudaGetSymbolAddress((void**)&pTD1,  g_TD1);
    cudaGetSymbolAddress((void**)&pTA45, g_TA45);
    cudaGetSymbolAddress((void**)&pTA6,  g_TA6);
    cudaGetSymbolAddress((void**)&pTS6,  g_TS6);
    cudaGetSymbolAddress((void**)&pTD6,  g_TD6);

    // launch 0: prep (concats + bias concats)
    prep_concat<<<128, 256>>>(W2, W3, W4, W5, b2, b3, b4, b5);

    // launch 1: batch A — everything that only needs prep:
    //   G = W1@C23, cst23 = b1@C23 + b23 (1-row GEMM), TA45, TA6, TS6, TD6
    {
        GBatch bt; bt.n = 6;
        bt.g[0] = { W1,     pC23,         nullptr, pG,    512, 256 };
        bt.g[1] = { b1,     pC23,         pb23,    pcst,  1,   256 };
        bt.g[2] = { a_tab,  pW45a,        pb45,    pTA45, NA1, 256 };
        bt.g[3] = { a_tab,  W6 + 128*128, b6,      pTA6,  NA1, 128 };
        bt.g[4] = { sd_tab, W6 + 256*128, nullptr, pTS6,  ND1, 128 };
        bt.g[5] = { qd_tab, W6 + 384*128, nullptr, pTD6,  ND1, 128 };
        int s = 0; bt.start[0] = 0;
        for (int i = 0; i < 6; i++) { s += (bt.g[i].M + 31) / 32; bt.start[i+1] = s; }
        gemm_batched<<<s, 256>>>(bt);
    }
    // launch 2: batch B — needs G/cst: TQ, TC, TS1, TD1
    {
        GBatch bt; bt.n = 4;
        bt.g[0] = { q_tab,  pG,           pcst,    pTQ,  NQ1, 256 };
        bt.g[1] = { c_tab,  pG + 128*256, nullptr, pTC,  NC1, 256 };
        bt.g[2] = { sd_tab, pG + 256*256, nullptr, pTS1, ND1, 256 };
        bt.g[3] = { qd_tab, pG + 384*256, nullptr, pTD1, ND1, 256 };
        int s = 0; bt.start[0] = 0;
        for (int i = 0; i < 4; i++) { s += (bt.g[i].M + 31) / 32; bt.start[i+1] = s; }
        gemm_batched<<<s, 256>>>(bt);
    }

    // launch 3: scan (this is the launch ncu profiles)
    cudaFuncSetAttribute(scan_kernel, cudaFuncAttributeMaxDynamicSharedMemorySize, SCAN_SMEM_BYTES);
    scan_kernel<<<128, 256, SCAN_SMEM_BYTES>>>(qi, ci, si, di, ai, knowledge,
                                               W2, W3, W4, W5, W6, Wf, bf, out);
}